// round 2
// baseline (speedup 1.0000x reference)
#include <cuda_runtime.h>
#include <math_constants.h>

#define FULL_MASK 0xFFFFFFFFu

// x: (32, 2, 513, 2048) fp32. channel 0 = magnitude, channel 1 = phase.
// rows = 32*513 = 16416, row length 2048.
// One warp per row, 3 rows per warp, double-buffered cp.async staging.
// 2736 blocks x 64 threads (2 warps) -> 5472 warps x 3 rows = 16416.

__device__ __forceinline__ void cp16(float4* dst, const float4* src) {
    unsigned d = (unsigned)__cvta_generic_to_shared(dst);
    asm volatile("cp.async.ca.shared.global [%0], [%1], 16;" :: "r"(d), "l"(src));
}

__device__ __forceinline__ size_t mag_offset(int row) {
    int b = row / 513;
    int f = row - b * 513;
    return (size_t)(b * 1026 + f) * 2048;   // ((b*2+0)*513+f)*2048
}

#define CE(i,j) { float lo_=fminf(v[i],v[j]), hi_=fmaxf(v[i],v[j]); v[i]=lo_; v[j]=hi_; }

__global__ __launch_bounds__(64, 7)
void spectral_sub_kernel(const float* __restrict__ x, float* __restrict__ out)
{
    __shared__ float4 sbuf[2][2][512];     // [buf][warp][f4] = 32 KB static

    const int lane = threadIdx.x & 31;
    const int warp = threadIdx.x >> 5;
    const int wg   = blockIdx.x * 2 + warp;    // [0, 5472)
    const int row0 = wg * 3;

    // ---- prologue: stage row0 into buffer 0 ----
    {
        const float4* mv = (const float4*)(x + mag_offset(row0));
        #pragma unroll
        for (int it = 0; it < 16; ++it)
            cp16(&sbuf[0][warp][it*32 + lane], &mv[it*32 + lane]);
        asm volatile("cp.async.commit_group;");
    }

    #pragma unroll
    for (int j = 0; j < 3; ++j) {
        // kick off next row's copy before waiting on the current one
        if (j < 2) {
            const float4* mv = (const float4*)(x + mag_offset(row0 + j + 1));
            #pragma unroll
            for (int it = 0; it < 16; ++it)
                cp16(&sbuf[(j+1)&1][warp][it*32 + lane], &mv[it*32 + lane]);
            asm volatile("cp.async.commit_group;");
            asm volatile("cp.async.wait_group 1;");   // current row complete, next in flight
        } else {
            asm volatile("cp.async.wait_group 0;");
        }
        // every lane reads only its own cp.async destinations -> no barrier needed

        const float4* __restrict__ S = sbuf[j&1][warp];
        const size_t moff = mag_offset(row0 + j);
        const float4* __restrict__ phv  = (const float4*)(x + moff + (size_t)513*2048);
        float4* __restrict__ outr = (float4*)(out + moff);
        float4* __restrict__ outi = (float4*)(out + moff + (size_t)513*2048);

        // ---- phase A: per-group (min1, min2) of squares, pure ALU ----
        float gm[8], gm2[8];
        #pragma unroll
        for (int g = 0; g < 8; ++g) {
            float4 a = S[(2*g  )*32 + lane];
            float4 c = S[(2*g+1)*32 + lane];
            float v0=a.x*a.x, v1=a.y*a.y, v2=a.z*a.z, v3=a.w*a.w;
            float v4=c.x*c.x, v5=c.y*c.y, v6=c.z*c.z, v7=c.w*c.w;
            float p1=fminf(v0,v1), p2=fmaxf(v0,v1);
            float q1=fminf(v2,v3), q2=fmaxf(v2,v3);
            float r1=fminf(v4,v5), r2=fmaxf(v4,v5);
            float s1=fminf(v6,v7), s2=fmaxf(v6,v7);
            float pq1=fminf(p1,q1), pq2=fminf(fmaxf(p1,q1), fminf(p2,q2));
            float rs1=fminf(r1,s1), rs2=fminf(fmaxf(r1,s1), fminf(r2,s2));
            gm[g]  = fminf(pq1, rs1);
            gm2[g] = fminf(fmaxf(pq1, rs1), fminf(pq2, rs2));
        }

        // ---- ascending extraction of the 32 smallest squares ----
        // Per-group consumption is ascending (global mins extracted in order),
        // so a 4-bit packed consumed-count per group suffices; full 8-sort rescan
        // only when a group's cached 2nd-min has been used up (rare).
        unsigned cnt = 0;
        float sum = 0.0f;
        #pragma unroll 1
        for (int iter = 0; iter < 32; ++iter) {
            float lmin = fminf(fminf(fminf(gm[0],gm[1]), fminf(gm[2],gm[3])),
                               fminf(fminf(gm[4],gm[5]), fminf(gm[6],gm[7])));
            float wmin = lmin;
            #pragma unroll
            for (int o = 16; o; o >>= 1)
                wmin = fminf(wmin, __shfl_xor_sync(FULL_MASK, wmin, o));
            sum += wmin;
            unsigned bal = __ballot_sync(FULL_MASK, lmin == wmin);
            if (lane == __ffs(bal) - 1) {           // single winner (ties resolved by lane id)
                int g = 7;
                #pragma unroll
                for (int i = 6; i >= 0; --i) if (gm[i] == lmin) g = i;
                float second = gm2[7];
                #pragma unroll
                for (int i = 6; i >= 0; --i) if (i == g) second = gm2[i];
                int n = (cnt >> (4*g)) & 0xF;       // consumed so far in group g
                cnt += 1u << (4*g);
                if (second >= 0.0f) {
                    // cheap path: promote cached 2nd-min, invalidate it
                    #pragma unroll
                    for (int i = 0; i < 8; ++i)
                        if (i == g) { gm[i] = second; gm2[i] = -1.0f; }
                } else {
                    // rare path: sort group g's 8 squares, take ranks n+1, n+2
                    float4 a = S[(2*g  )*32 + lane];
                    float4 c = S[(2*g+1)*32 + lane];
                    float v[8] = {a.x*a.x, a.y*a.y, a.z*a.z, a.w*a.w,
                                  c.x*c.x, c.y*c.y, c.z*c.z, c.w*c.w};
                    CE(0,1) CE(2,3) CE(4,5) CE(6,7)
                    CE(0,2) CE(1,3) CE(4,6) CE(5,7)
                    CE(1,2) CE(5,6) CE(0,4) CE(3,7)
                    CE(1,5) CE(2,6)
                    CE(1,4) CE(3,6)
                    CE(2,4) CE(3,5)
                    CE(3,4)
                    float nmin = CUDART_INF_F, nsec = CUDART_INF_F;
                    #pragma unroll
                    for (int rix = 0; rix < 8; ++rix) {
                        if (rix == n + 1) nmin = v[rix];
                        if (rix == n + 2) nsec = v[rix];
                    }
                    #pragma unroll
                    for (int i = 0; i < 8; ++i)
                        if (i == g) { gm[i] = nmin; gm2[i] = nsec; }
                }
            }
        }
        const float noise = sum * (1.0f / 32.0f);

        // ---- pass 2: stream phase, emit real/imag ----
        float4 ph = phv[lane];
        #pragma unroll
        for (int it = 0; it < 16; ++it) {
            float4 phn;
            if (it < 15) phn = phv[(it + 1)*32 + lane];

            float4 m4 = S[it*32 + lane];
            float4 re, im;
            float m, sn, cs;
            m = fmaxf(m4.x - noise, 0.0f); __sincosf(ph.x, &sn, &cs); re.x = m*cs; im.x = m*sn;
            m = fmaxf(m4.y - noise, 0.0f); __sincosf(ph.y, &sn, &cs); re.y = m*cs; im.y = m*sn;
            m = fmaxf(m4.z - noise, 0.0f); __sincosf(ph.z, &sn, &cs); re.z = m*cs; im.z = m*sn;
            m = fmaxf(m4.w - noise, 0.0f); __sincosf(ph.w, &sn, &cs); re.w = m*cs; im.w = m*sn;

            outr[it*32 + lane] = re;
            outi[it*32 + lane] = im;
            ph = phn;
        }
    }
}

extern "C" void kernel_launch(void* const* d_in, const int* in_sizes, int n_in,
                              void* d_out, int out_size)
{
    const float* x = (const float*)d_in[0];
    // d_in[1] = n_avg (int32, fixed at 32 for this problem; algorithm specialized for k==32)
    float* out = (float*)d_out;

    // 2736 blocks x 2 warps x 3 rows = 16416 rows
    spectral_sub_kernel<<<2736, 64>>>(x, out);
}

// round 3
// speedup vs baseline: 1.3671x; 1.3671x over previous
#include <cuda_runtime.h>
#include <math_constants.h>

#define FULL_MASK 0xFFFFFFFFu

// x: (32, 2, 513, 2048) fp32. channel 0 = magnitude, channel 1 = phase.
// rows = 32*513 = 16416, row length 2048. One warp per row, no smem.
// Phase A: batched register loads (MLP=8) + per-lane (min1,min2) of 8 groups.
// Extraction: 32 iters with REDUX.MIN on float-as-uint (squares >= 0).
// Pass 2: mag re-read (L2-hot), phase/out with streaming cache ops, 8-wide load batches.

#define CE(i,j) { float lo_=fminf(v[i],v[j]), hi_=fmaxf(v[i],v[j]); v[i]=lo_; v[j]=hi_; }

__global__ __launch_bounds__(128, 7)
void spectral_sub_kernel(const float* __restrict__ x, float* __restrict__ out)
{
    const int lane = threadIdx.x & 31;
    const int warp = threadIdx.x >> 5;
    const int row  = blockIdx.x * 4 + warp;          // [0, 16416)

    const int b = row / 513;
    const int f = row - b * 513;
    const size_t moff = (size_t)(b * 1026 + f) * 2048;       // ((b*2+0)*513+f)*2048
    const float4* __restrict__ magv = (const float4*)(x + moff);
    const float4* __restrict__ phv  = (const float4*)(x + moff + (size_t)513 * 2048);
    float4* __restrict__ outr = (float4*)(out + moff);
    float4* __restrict__ outi = (float4*)(out + moff + (size_t)513 * 2048);

    // ---- Phase A: per-lane (min1,min2) of squares for 8 groups of 8 values ----
    float gm[8], gm2[8];
    #pragma unroll
    for (int h = 0; h < 2; ++h) {
        float4 d[8];
        #pragma unroll
        for (int c = 0; c < 8; ++c)                   // 8 LDG.128 batched -> MLP 8
            d[c] = magv[(h * 8 + c) * 32 + lane];
        #pragma unroll
        for (int gg = 0; gg < 4; ++gg) {
            const int g = h * 4 + gg;
            float4 a = d[2 * gg], c4 = d[2 * gg + 1];
            float v0=a.x*a.x,  v1=a.y*a.y,  v2=a.z*a.z,  v3=a.w*a.w;
            float v4=c4.x*c4.x, v5=c4.y*c4.y, v6=c4.z*c4.z, v7=c4.w*c4.w;
            float p1=fminf(v0,v1), p2=fmaxf(v0,v1);
            float q1=fminf(v2,v3), q2=fmaxf(v2,v3);
            float r1=fminf(v4,v5), r2=fmaxf(v4,v5);
            float s1=fminf(v6,v7), s2=fmaxf(v6,v7);
            float pq1=fminf(p1,q1), pq2=fminf(fmaxf(p1,q1), fminf(p2,q2));
            float rs1=fminf(r1,s1), rs2=fminf(fmaxf(r1,s1), fminf(r2,s2));
            gm[g]  = fminf(pq1, rs1);
            gm2[g] = fminf(fmaxf(pq1, rs1), fminf(pq2, rs2));
        }
    }

    // ---- ascending extraction of the 32 smallest squares ----
    unsigned cnt = 0;          // 4-bit consumed count per group
    float sum = 0.0f;
    #pragma unroll 1
    for (int iter = 0; iter < 32; ++iter) {
        float lmin = fminf(fminf(fminf(gm[0],gm[1]), fminf(gm[2],gm[3])),
                           fminf(fminf(gm[4],gm[5]), fminf(gm[6],gm[7])));
        unsigned u = __float_as_uint(lmin);           // >=0 floats: bits are order-isomorphic
        unsigned w = __reduce_min_sync(FULL_MASK, u); // REDUX.MIN, replaces 5-shfl butterfly
        sum += __uint_as_float(w);
        unsigned bal = __ballot_sync(FULL_MASK, u == w);
        if (lane == __ffs(bal) - 1) {                 // single winner pops its min
            const float lm = __uint_as_float(w);
            int g = 7;
            #pragma unroll
            for (int i = 6; i >= 0; --i) if (gm[i] == lm) g = i;
            float second = gm2[7];
            #pragma unroll
            for (int i = 6; i >= 0; --i) if (i == g) second = gm2[i];
            const int n = (cnt >> (4 * g)) & 0xF;
            cnt += 1u << (4 * g);
            if (second >= 0.0f) {
                // cheap path: promote cached 2nd-min, invalidate it
                #pragma unroll
                for (int i = 0; i < 8; ++i)
                    if (i == g) { gm[i] = second; gm2[i] = -1.0f; }
            } else {
                // rare path: re-read group g (L2-hot), sort 8, take ranks n+1, n+2
                float4 a  = magv[(2 * g    ) * 32 + lane];
                float4 c4 = magv[(2 * g + 1) * 32 + lane];
                float v[8] = {a.x*a.x, a.y*a.y, a.z*a.z, a.w*a.w,
                              c4.x*c4.x, c4.y*c4.y, c4.z*c4.z, c4.w*c4.w};
                CE(0,1) CE(2,3) CE(4,5) CE(6,7)
                CE(0,2) CE(1,3) CE(4,6) CE(5,7)
                CE(1,2) CE(5,6) CE(0,4) CE(3,7)
                CE(1,5) CE(2,6)
                CE(1,4) CE(3,6)
                CE(2,4) CE(3,5)
                CE(3,4)
                float nmin = CUDART_INF_F, nsec = CUDART_INF_F;
                #pragma unroll
                for (int rix = 0; rix < 8; ++rix) {
                    if (rix == n + 1) nmin = v[rix];
                    if (rix == n + 2) nsec = v[rix];
                }
                #pragma unroll
                for (int i = 0; i < 8; ++i)
                    if (i == g) { gm[i] = nmin; gm2[i] = nsec; }
            }
        }
    }
    const float noise = sum * (1.0f / 32.0f);

    // ---- Pass 2: mag re-read (L2) + phase stream -> real/imag out ----
    #pragma unroll
    for (int s = 0; s < 4; ++s) {
        float4 m4[4], p4[4];
        #pragma unroll
        for (int c = 0; c < 4; ++c) {                 // 8 LDGs batched -> MLP 8
            m4[c] = magv[(s * 4 + c) * 32 + lane];
            p4[c] = __ldcs(&phv[(s * 4 + c) * 32 + lane]);
        }
        #pragma unroll
        for (int c = 0; c < 4; ++c) {
            float4 re, im;
            float m, sn, cs;
            m = fmaxf(m4[c].x - noise, 0.0f); __sincosf(p4[c].x, &sn, &cs); re.x = m*cs; im.x = m*sn;
            m = fmaxf(m4[c].y - noise, 0.0f); __sincosf(p4[c].y, &sn, &cs); re.y = m*cs; im.y = m*sn;
            m = fmaxf(m4[c].z - noise, 0.0f); __sincosf(p4[c].z, &sn, &cs); re.z = m*cs; im.z = m*sn;
            m = fmaxf(m4[c].w - noise, 0.0f); __sincosf(p4[c].w, &sn, &cs); re.w = m*cs; im.w = m*sn;
            __stcs(&outr[(s * 4 + c) * 32 + lane], re);
            __stcs(&outi[(s * 4 + c) * 32 + lane], im);
        }
    }
}

extern "C" void kernel_launch(void* const* d_in, const int* in_sizes, int n_in,
                              void* d_out, int out_size)
{
    const float* x = (const float*)d_in[0];
    // d_in[1] = n_avg (int32, fixed at 32 for this problem; algorithm specialized for k==32)
    float* out = (float*)d_out;

    // 16416 rows / 4 warps per block
    spectral_sub_kernel<<<4104, 128>>>(x, out);
}

// round 4
// speedup vs baseline: 2.0966x; 1.5336x over previous
#include <cuda_runtime.h>
#include <math_constants.h>

#define FULL_MASK 0xFFFFFFFFu
#define INF_BITS  0x7f800000u

// x: (32, 2, 513, 2048) fp32. channel 0 = magnitude, channel 1 = phase.
// rows = 32*513 = 16416, row length 2048. One warp per row, no smem.
// Top-32-smallest-squares: per-lane branchless sorted-6 list + cheap warp
// extraction (REDUX.MIN); exact rebuild-on-exhaust (~1.2% of rows).

// Branchless insert of s into sorted list m0<=...<=m5 (keep 6 smallest).
// Each line reads only pre-update values (top-down order).
#define INS(sv) do { float s_ = (sv);            \
    m5 = fminf(m5, fmaxf(m4, s_));               \
    m4 = fminf(m4, fmaxf(m3, s_));               \
    m3 = fminf(m3, fmaxf(m2, s_));               \
    m2 = fminf(m2, fmaxf(m1, s_));               \
    m1 = fminf(m1, fmaxf(m0, s_));               \
    m0 = fminf(m0, s_); } while (0)

__global__ __launch_bounds__(128, 8)   // force <=64 regs -> 32 warps/SM
void spectral_sub_kernel(const float* __restrict__ x, float* __restrict__ out)
{
    const int lane = threadIdx.x & 31;
    const int warp = threadIdx.x >> 5;
    const int row  = blockIdx.x * 4 + warp;          // [0, 16416)

    const int b = row / 513;
    const int f = row - b * 513;
    const size_t moff = (size_t)(b * 1026 + f) * 2048;       // ((b*2+0)*513+f)*2048
    const float4* __restrict__ magv = (const float4*)(x + moff);
    const float4* __restrict__ phv  = (const float4*)(x + moff + (size_t)513 * 2048);
    float4* __restrict__ outr = (float4*)(out + moff);
    float4* __restrict__ outi = (float4*)(out + moff + (size_t)513 * 2048);

    // ---- Phase A: per-lane sorted-6 of the squares of this lane's 64 values ----
    float m0 = CUDART_INF_F, m1 = CUDART_INF_F, m2 = CUDART_INF_F,
          m3 = CUDART_INF_F, m4 = CUDART_INF_F, m5 = CUDART_INF_F;

    #pragma unroll
    for (int h = 0; h < 4; ++h) {
        float4 d[4];
        #pragma unroll
        for (int c = 0; c < 4; ++c)                   // 4 LDG.128 batched (MLP=4)
            d[c] = magv[(h * 4 + c) * 32 + lane];
        #pragma unroll
        for (int c = 0; c < 4; ++c) {
            INS(d[c].x * d[c].x);
            INS(d[c].y * d[c].y);
            INS(d[c].z * d[c].z);
            INS(d[c].w * d[c].w);
        }
    }

    // ---- prefetch pass-2 batch 0 (hidden behind the extraction chain) ----
    float4 pm[4], pp[4];
    #pragma unroll
    for (int c = 0; c < 4; ++c) {
        pm[c] = magv[c * 32 + lane];
        pp[c] = __ldcs(&phv[c * 32 + lane]);
    }

    // ---- extraction: 32 ascending pops of the warp-wide minimum ----
    // squares >= 0 -> float bits are order-isomorphic to u32.
    float sum = 0.0f;
    #pragma unroll 1
    for (int iter = 0; iter < 32; ++iter) {
        unsigned u = __float_as_uint(m0);
        unsigned w = __reduce_min_sync(FULL_MASK, u);     // REDUX.MIN
        sum += __uint_as_float(w);
        unsigned bal = __ballot_sync(FULL_MASK, u == w);  // tie-exact: one pop/iter
        if (lane == __ffs(bal) - 1) {
            m0 = m1; m1 = m2; m2 = m3; m3 = m4; m4 = m5; m5 = CUDART_INF_F;
            if (__float_as_uint(m0) == INF_BITS) {
                // exact rebuild (~1.2% of rows): this lane's next-6 smallest > t.
                // L2-hot reload of the lane's own 64 values.
                const float t = __uint_as_float(w);
                #pragma unroll
                for (int c = 0; c < 16; ++c) {
                    float4 dv = magv[c * 32 + lane];
                    float s;
                    s = dv.x * dv.x; s = (s > t) ? s : CUDART_INF_F; INS(s);
                    s = dv.y * dv.y; s = (s > t) ? s : CUDART_INF_F; INS(s);
                    s = dv.z * dv.z; s = (s > t) ? s : CUDART_INF_F; INS(s);
                    s = dv.w * dv.w; s = (s > t) ? s : CUDART_INF_F; INS(s);
                }
            }
        }
    }
    const float noise = sum * (1.0f / 32.0f);

    // ---- Pass 2: mag re-read (L2-hot) + streamed phase -> real/imag ----
    #pragma unroll
    for (int s = 0; s < 4; ++s) {
        float4 mm[4], ph[4];
        if (s == 0) {
            #pragma unroll
            for (int c = 0; c < 4; ++c) { mm[c] = pm[c]; ph[c] = pp[c]; }
        } else {
            #pragma unroll
            for (int c = 0; c < 4; ++c) {             // 8 LDGs batched (MLP=8)
                mm[c] = magv[(s * 4 + c) * 32 + lane];
                ph[c] = __ldcs(&phv[(s * 4 + c) * 32 + lane]);
            }
        }
        #pragma unroll
        for (int c = 0; c < 4; ++c) {
            float4 re, im;
            float m, sn, cs;
            m = fmaxf(mm[c].x - noise, 0.0f); __sincosf(ph[c].x, &sn, &cs); re.x = m*cs; im.x = m*sn;
            m = fmaxf(mm[c].y - noise, 0.0f); __sincosf(ph[c].y, &sn, &cs); re.y = m*cs; im.y = m*sn;
            m = fmaxf(mm[c].z - noise, 0.0f); __sincosf(ph[c].z, &sn, &cs); re.z = m*cs; im.z = m*sn;
            m = fmaxf(mm[c].w - noise, 0.0f); __sincosf(ph[c].w, &sn, &cs); re.w = m*cs; im.w = m*sn;
            __stcs(&outr[(s * 4 + c) * 32 + lane], re);
            __stcs(&outi[(s * 4 + c) * 32 + lane], im);
        }
    }
}

extern "C" void kernel_launch(void* const* d_in, const int* in_sizes, int n_in,
                              void* d_out, int out_size)
{
    const float* x = (const float*)d_in[0];
    // d_in[1] = n_avg (int32, fixed at 32 for this problem; algorithm specialized for k==32)
    float* out = (float*)d_out;

    // 16416 rows / 4 warps per block
    spectral_sub_kernel<<<4104, 128>>>(x, out);
}